// round 12
// baseline (speedup 1.0000x reference)
#include <cuda_runtime.h>
#include <cuda_bf16.h>
#include <cstdint>
#include <math.h>

#define BB 64
#define TT 256
#define HH 256
#define DD 128

// ---- scratch (device globals: no allocation allowed) ----
__device__ float g_xproj[(size_t)BB * TT * 768];   // [b*T+t][768]
__device__ float g_enc[(size_t)BB * TT * HH];      // [b*T+t][256]

// output layout (floats), concatenated in reference return order:
// mean_z [64,256,8] | chol_z [8,64,256,256] | mean_x [16384,8] | cov_x [16384,8,8]
#define OFF_MZ   0ull
#define OFF_CHOL 131072ull
#define OFF_MX   33685504ull
#define OFF_CX   33816576ull

// GRU dynamic smem layout (floats):
//   [0, 1024)      h_s  [phase][batch][HH]
//   [1024, 19456)  Wn   64 rows * 288 stride (gate-n weights)
// STR=288: granule idx = j*72+ks ≡ 8j+ks (mod 32) -> bijective over
// a warp's 4 j x 8 ks accesses -> conflict-free LDS.128.
#define GRU_WN_STR   288
#define GRU_SMEM_BYTES  ((1024 + 64 * GRU_WN_STR) * 4)   // 77824

// ============================================================
// 1) x_proj = y @ W_ih^T + b_ih : [16384,128] x [128,768]
// ============================================================
__global__ void __launch_bounds__(256) xproj_kernel(const float* __restrict__ y,
                                                    const float* __restrict__ Wih,
                                                    const float* __restrict__ bih)
{
    __shared__ float As[64][68];   // [k][m]
    __shared__ float Bs[64][68];   // [k][n]
    const int tid = threadIdx.x;
    const int tx = tid & 15;       // n/4
    const int ty = tid >> 4;       // m/4
    const int m0 = blockIdx.x * 64;
    const int n0 = blockIdx.y * 64;

    float acc[4][4];
#pragma unroll
    for (int i = 0; i < 4; i++)
#pragma unroll
        for (int j = 0; j < 4; j++) acc[i][j] = 0.f;

    for (int kp = 0; kp < 128; kp += 64) {
        __syncthreads();
#pragma unroll
        for (int l = 0; l < 4; l++) {
            int lin = tid + l * 256;
            int row = lin >> 4;
            int kq  = lin & 15;
            float4 va = *(const float4*)(y   + (size_t)(m0 + row) * DD + kp + kq * 4);
            float4 vb = *(const float4*)(Wih + (size_t)(n0 + row) * DD + kp + kq * 4);
            As[kq * 4 + 0][row] = va.x; As[kq * 4 + 1][row] = va.y;
            As[kq * 4 + 2][row] = va.z; As[kq * 4 + 3][row] = va.w;
            Bs[kq * 4 + 0][row] = vb.x; Bs[kq * 4 + 1][row] = vb.y;
            Bs[kq * 4 + 2][row] = vb.z; Bs[kq * 4 + 3][row] = vb.w;
        }
        __syncthreads();
#pragma unroll
        for (int k = 0; k < 64; k++) {
            float4 av = *(const float4*)&As[k][ty * 4];
            float4 bv = *(const float4*)&Bs[k][tx * 4];
            float a[4] = {av.x, av.y, av.z, av.w};
            float b[4] = {bv.x, bv.y, bv.z, bv.w};
#pragma unroll
            for (int i = 0; i < 4; i++)
#pragma unroll
                for (int j = 0; j < 4; j++) acc[i][j] = fmaf(a[i], b[j], acc[i][j]);
        }
    }
#pragma unroll
    for (int j = 0; j < 4; j++) {
        float b = bih[n0 + tx * 4 + j];
#pragma unroll
        for (int i = 0; i < 4; i++) acc[i][j] += b;
    }
#pragma unroll
    for (int i = 0; i < 4; i++) {
        float* o = g_xproj + (size_t)(m0 + ty * 4 + i) * 768 + n0 + tx * 4;
        *(float4*)o = make_float4(acc[i][0], acc[i][1], acc[i][2], acc[i][3]);
    }
}

// ============================================================
// 2) GRU: 32 clusters x 4 CTAs, 2 batches/cluster.
//    j = tid>>3 (unit), ks = tid&7; thread owns k-words
//    {ks*4 + q*32 + c} (interleaved, conflict-free). Unit's 8
//    partials reduce via shfl_xor in-warp; owners (ks==0) do
//    activations + cluster broadcast. Gates r,z in regs; gate n
//    in SMEM. chol zero-fill trickled (t<128).
// ============================================================
__global__ void __cluster_dims__(4, 1, 1) __launch_bounds__(512, 1)
gru_kernel(const float* __restrict__ Whh, const float* __restrict__ bhh,
           float4* __restrict__ chol4)
{
    extern __shared__ float dsm[];
    float* h_s = dsm;            // [(ph*2 + b)*HH + idx]
    float* Wn  = dsm + 1024;     // [j*GRU_WN_STR + k]

    const int tid  = threadIdx.x;
    const int j    = tid >> 3;                 // 0..63 hidden unit
    const int ks   = tid & 7;                  // 0..7 interleave slot
    const int rank = blockIdx.x & 3;
    const int u0   = rank * 64;
    const int bg   = (blockIdx.x >> 2) * 2;    // global batch base
    const bool owner = (ks == 0);

    // register-resident W for gates r,z: interleaved k-chunks
    float W[2][32];
#pragma unroll
    for (int g = 0; g < 2; g++) {
        const float* base = Whh + (size_t)(g * HH + u0 + j) * HH + ks * 4;
#pragma unroll
        for (int q = 0; q < 8; q++) {
            float4 v = *(const float4*)(base + q * 32);
            W[g][4 * q + 0] = v.x; W[g][4 * q + 1] = v.y;
            W[g][4 * q + 2] = v.z; W[g][4 * q + 3] = v.w;
        }
    }
    // SMEM-resident gate-n weights
    {
        const float* base = Whh + (size_t)(2 * HH + u0 + j) * HH + ks * 4;
        float* dst = &Wn[j * GRU_WN_STR + ks * 4];
#pragma unroll
        for (int q = 0; q < 8; q++)
            *(float4*)(dst + q * 32) = *(const float4*)(base + q * 32);
    }
    float bh0 = 0.f, bh1 = 0.f, bh2 = 0.f;
    if (owner) {
        bh0 = bhh[u0 + j];
        bh1 = bhh[HH + u0 + j];
        bh2 = bhh[2 * HH + u0 + j];
    }
    for (int i = tid; i < 2 * 2 * HH; i += 512) h_s[i] = 0.f;

    uint32_t hbase;
    asm("{ .reg .u64 t; cvta.to.shared.u64 t, %1; cvt.u32.u64 %0, t; }"
        : "=r"(hbase) : "l"((void*)h_s));

    const size_t zbase = (size_t)blockIdx.x * 512 + tid;
    const float4 zf4 = make_float4(0.f, 0.f, 0.f, 0.f);

    __syncthreads();
    asm volatile("barrier.cluster.arrive.aligned;" ::: "memory");
    asm volatile("barrier.cluster.wait.aligned;" ::: "memory");

    for (int t = 0; t < TT; t++) {
        const int ph = t & 1;
        // zero-fill trickle: 128 steps x 65536 float4 = whole chol region
        if (t < 128) chol4[(size_t)t * 65536 + zbase] = zf4;

        // owners prefetch x_proj for both batches
        float xr0 = 0.f, xz0 = 0.f, xn0 = 0.f, xr1 = 0.f, xz1 = 0.f, xn1 = 0.f;
        if (owner) {
            const float* xp0 = g_xproj + ((size_t)(bg + 0) * TT + t) * 768 + u0 + j;
            const float* xp1 = g_xproj + ((size_t)(bg + 1) * TT + t) * 768 + u0 + j;
            xr0 = xp0[0]; xz0 = xp0[HH]; xn0 = xp0[2 * HH];
            xr1 = xp1[0]; xz1 = xp1[HH]; xn1 = xp1[2 * HH];
        }
        // partial dots: 3 gates x 2 batches over interleaved k-chunks
        float a00 = 0.f, a01 = 0.f, a10 = 0.f, a11 = 0.f, a20 = 0.f, a21 = 0.f;
        const float* h0p = &h_s[(ph * 2 + 0) * HH + ks * 4];
        const float* h1p = &h_s[(ph * 2 + 1) * HH + ks * 4];
        const float* wnp = &Wn[j * GRU_WN_STR + ks * 4];
#pragma unroll
        for (int q = 0; q < 8; q++) {
            float4 va = *(const float4*)(h0p + q * 32);
            float4 vb = *(const float4*)(h1p + q * 32);
            float4 wn = *(const float4*)(wnp + q * 32);
            float ha[4] = {va.x, va.y, va.z, va.w};
            float hb[4] = {vb.x, vb.y, vb.z, vb.w};
            float wnn[4] = {wn.x, wn.y, wn.z, wn.w};
#pragma unroll
            for (int c = 0; c < 4; c++) {
                float w0 = W[0][4 * q + c], w1 = W[1][4 * q + c], w2 = wnn[c];
                a00 = fmaf(w0, ha[c], a00); a01 = fmaf(w0, hb[c], a01);
                a10 = fmaf(w1, ha[c], a10); a11 = fmaf(w1, hb[c], a11);
                a20 = fmaf(w2, ha[c], a20); a21 = fmaf(w2, hb[c], a21);
            }
        }
        // butterfly reduce across the 8 lanes of this unit (same warp)
#pragma unroll
        for (int m = 4; m >= 1; m >>= 1) {
            a00 += __shfl_xor_sync(0xffffffffu, a00, m);
            a01 += __shfl_xor_sync(0xffffffffu, a01, m);
            a10 += __shfl_xor_sync(0xffffffffu, a10, m);
            a11 += __shfl_xor_sync(0xffffffffu, a11, m);
            a20 += __shfl_xor_sync(0xffffffffu, a20, m);
            a21 += __shfl_xor_sync(0xffffffffu, a21, m);
        }
        if (owner) {
            // batch 0
            float r0 = 1.f / (1.f + expf(-(xr0 + a00 + bh0)));
            float z0 = 1.f / (1.f + expf(-(xz0 + a10 + bh1)));
            float n0 = tanhf(xn0 + r0 * (a20 + bh2));
            float h0old = h_s[(ph * 2 + 0) * HH + u0 + j];
            float h0new = fmaf(z0, h0old - n0, n0);
            // batch 1
            float r1 = 1.f / (1.f + expf(-(xr1 + a01 + bh0)));
            float z1 = 1.f / (1.f + expf(-(xz1 + a11 + bh1)));
            float n1 = tanhf(xn1 + r1 * (a21 + bh2));
            float h1old = h_s[(ph * 2 + 1) * HH + u0 + j];
            float h1new = fmaf(z1, h1old - n1, n1);

            g_enc[((size_t)(bg + 0) * TT + t) * HH + u0 + j] = h0new;
            g_enc[((size_t)(bg + 1) * TT + t) * HH + u0 + j] = h1new;

            uint32_t l0 = hbase + (uint32_t)((((ph ^ 1) * 2 + 0) * HH + u0 + j) * 4);
            uint32_t l1 = l0 + HH * 4;
#pragma unroll
            for (int p = 0; p < 4; p++) {
                uint32_t r0a, r1a;
                asm("mapa.shared::cluster.u32 %0, %1, %2;" : "=r"(r0a) : "r"(l0), "r"(p));
                asm("mapa.shared::cluster.u32 %0, %1, %2;" : "=r"(r1a) : "r"(l1), "r"(p));
                asm volatile("st.shared::cluster.f32 [%0], %1;" :: "r"(r0a), "f"(h0new));
                asm volatile("st.shared::cluster.f32 [%0], %1;" :: "r"(r1a), "f"(h1new));
            }
        }
        asm volatile("barrier.cluster.arrive.aligned;" ::: "memory");
        asm volatile("barrier.cluster.wait.aligned;" ::: "memory");
    }
}

// ============================================================
// 3) heads: enc[16384,256] x W_all^T[256,96] + transforms + scatter
//    r: [0,8)=mean_z [8,16)=mean_x [16,32)=bd_z [32,96)=cov_x
//    Anchor (mean_x[b,0,:2]) computed in a per-block pre-pass.
// ============================================================
__global__ void __launch_bounds__(384) heads_kernel(
    const float* __restrict__ Wmz, const float* __restrict__ bmz,
    const float* __restrict__ Wmx, const float* __restrict__ bmx,
    const float* __restrict__ Wpz, const float* __restrict__ bpz,
    const float* __restrict__ Wcx, const float* __restrict__ bcx,
    float* __restrict__ out)
{
    __shared__ float encsm[256];
    __shared__ float red[384];
    __shared__ float anchor_sm[2];

    const int tid = threadIdx.x;
    const int r  = tid % 96;
    const int kc = tid / 96;

    const float* wrow;
    float bias;
    if (r < 8)       { wrow = Wmz + (size_t)r * HH;        bias = bmz[r]; }
    else if (r < 16) { wrow = Wmx + (size_t)(r - 8) * HH;  bias = bmx[r - 8]; }
    else if (r < 32) { wrow = Wpz + (size_t)(r - 16) * HH; bias = bpz[r - 16]; }
    else             { wrow = Wcx + (size_t)(r - 32) * HH; bias = bcx[r - 32]; }

    float W[64];
    {
        const float4* wp = (const float4*)(wrow + kc * 64);
#pragma unroll
        for (int q = 0; q < 16; q++) {
            float4 v = wp[q];
            W[4 * q + 0] = v.x; W[4 * q + 1] = v.y;
            W[4 * q + 2] = v.z; W[4 * q + 3] = v.w;
        }
    }

    const int row0 = blockIdx.x * 128;
    const int bbase = (blockIdx.x >> 1) << 8;   // t=0 row of this block's batch

    // anchor pre-pass: mean_x[b, 0, 0:2] (incl. bias)
    {
        if (tid < 64)
            *(float4*)&encsm[tid * 4] = *(const float4*)(g_enc + (size_t)bbase * HH + tid * 4);
        __syncthreads();
        float s = 0.f;
        const float4* ev = (const float4*)&encsm[kc * 64];
#pragma unroll
        for (int q = 0; q < 16; q++) {
            float4 v = ev[q];
            s = fmaf(W[4 * q + 0], v.x, s);
            s = fmaf(W[4 * q + 1], v.y, s);
            s = fmaf(W[4 * q + 2], v.z, s);
            s = fmaf(W[4 * q + 3], v.w, s);
        }
        red[kc * 96 + r] = s;
        __syncthreads();
        if (tid == 8 || tid == 9) {
            anchor_sm[tid - 8] =
                red[tid] + red[96 + tid] + red[192 + tid] + red[288 + tid] + bias;
        }
    }

    for (int i = 0; i < 128; i++) {
        const int row = row0 + i;
        __syncthreads();
        if (tid < 64) {
            *(float4*)&encsm[tid * 4] = *(const float4*)(g_enc + (size_t)row * HH + tid * 4);
        }
        __syncthreads();
        float s = 0.f;
        const float4* ev = (const float4*)&encsm[kc * 64];
#pragma unroll
        for (int q = 0; q < 16; q++) {
            float4 v = ev[q];
            s = fmaf(W[4 * q + 0], v.x, s);
            s = fmaf(W[4 * q + 1], v.y, s);
            s = fmaf(W[4 * q + 2], v.z, s);
            s = fmaf(W[4 * q + 3], v.w, s);
        }
        red[kc * 96 + r] = s;
        __syncthreads();
        if (tid < 96) {
            float v = red[tid] + red[96 + tid] + red[192 + tid] + red[288 + tid] + bias;
            const int b = row >> 8, t = row & 255;
            if (tid < 8) {
                out[OFF_MZ + (size_t)row * 8 + tid] = v;
            } else if (tid < 16) {
                int d = tid - 8;
                float a = (d < 2) ? anchor_sm[d] : 0.f;
                out[OFF_MX + (size_t)row * 8 + d] = v - a;
            } else if (tid < 32) {
                int d = tid - 16;
                if (d < 8) {
                    float sp = (v > 20.f) ? v : log1pf(expf(v));
                    out[OFF_CHOL + (((size_t)d * BB + b) * TT + t) * TT + t] = sp;
                } else {
                    int dz = d - 8;
                    if (t < TT - 1)
                        out[OFF_CHOL + (((size_t)dz * BB + b) * TT + t) * TT + (t + 1)] = v;
                }
            } else {
                out[OFF_CX + (size_t)row * 64 + (tid - 32)] = v;
            }
        }
    }
}

extern "C" void kernel_launch(void* const* d_in, const int* in_sizes, int n_in,
                              void* d_out, int out_size)
{
    const float* y    = (const float*)d_in[0];
    const float* Wih  = (const float*)d_in[1];
    const float* Whh  = (const float*)d_in[2];
    const float* bih  = (const float*)d_in[3];
    const float* bhh  = (const float*)d_in[4];
    const float* Wmz  = (const float*)d_in[5];
    const float* bmz  = (const float*)d_in[6];
    const float* Wmx  = (const float*)d_in[7];
    const float* bmx  = (const float*)d_in[8];
    const float* Wpz  = (const float*)d_in[9];
    const float* bpz  = (const float*)d_in[10];
    const float* Wcx  = (const float*)d_in[11];
    const float* bcx  = (const float*)d_in[12];
    float* out = (float*)d_out;

    cudaFuncSetAttribute(gru_kernel, cudaFuncAttributeMaxDynamicSharedMemorySize,
                         GRU_SMEM_BYTES);

    dim3 gx(256, 12);
    xproj_kernel<<<gx, 256>>>(y, Wih, bih);

    gru_kernel<<<128, 512, GRU_SMEM_BYTES>>>(Whh, bhh, (float4*)(out + OFF_CHOL));

    heads_kernel<<<128, 384>>>(Wmz, bmz, Wmx, bmx, Wpz, bpz, Wcx, bcx, out);
}

// round 15
// speedup vs baseline: 1.3301x; 1.3301x over previous
#include <cuda_runtime.h>
#include <cuda_bf16.h>
#include <cstdint>
#include <math.h>

#define BB 64
#define TT 256
#define HH 256
#define DD 128

// ---- scratch (device globals: no allocation allowed) ----
__device__ float g_xproj[(size_t)BB * TT * 768];   // [b*T+t][768]
__device__ float g_enc[(size_t)BB * TT * HH];      // [b*T+t][256]

// output layout (floats), concatenated in reference return order:
// mean_z [64,256,8] | chol_z [8,64,256,256] | mean_x [16384,8] | cov_x [16384,8,8]
#define OFF_MZ   0ull
#define OFF_CHOL 131072ull
#define OFF_MX   33685504ull
#define OFF_CX   33816576ull
#define CHOL_F4  8388608   // 33554432 floats / 4

// GRU dynamic smem layout (floats):
//   [0, 1024)     h_s   [phase][batch][HH]
//   [1024, 4160)  red   64 rows * 49 stride
//   [4160, 20800) Wn    64 rows * 260 stride (gate-n weights)
#define GRU_HS_OFF   0
#define GRU_RED_OFF  1024
#define GRU_WN_OFF   4160
#define GRU_WN_STR   260
#define GRU_SMEM_BYTES  ((GRU_WN_OFF + 64 * GRU_WN_STR) * 4)   // 83200

// ============================================================
// 1) x_proj = y @ W_ih^T + b_ih : [16384,128] x [128,768]
//    + fused chol_z zero-fill (HBM stores hidden behind FMA work)
// ============================================================
__global__ void __launch_bounds__(256) xproj_kernel(const float* __restrict__ y,
                                                    const float* __restrict__ Wih,
                                                    const float* __restrict__ bih,
                                                    float4* __restrict__ chol4)
{
    __shared__ float As[64][68];   // [k][m]
    __shared__ float Bs[64][68];   // [k][n]
    const int tid = threadIdx.x;
    const int tx = tid & 15;       // n/4
    const int ty = tid >> 4;       // m/4
    const int m0 = blockIdx.x * 64;
    const int n0 = blockIdx.y * 64;

    // fused zero-fill of the chol region: 3072 CTAs x 2731 float4
    {
        const int bid = blockIdx.y * gridDim.x + blockIdx.x;   // 0..3071
        const size_t start = (size_t)bid * 2731;
        const float4 z = make_float4(0.f, 0.f, 0.f, 0.f);
        for (int k = tid; k < 2731; k += 256) {
            size_t idx = start + k;
            if (idx < CHOL_F4) chol4[idx] = z;
        }
    }

    float acc[4][4];
#pragma unroll
    for (int i = 0; i < 4; i++)
#pragma unroll
        for (int j = 0; j < 4; j++) acc[i][j] = 0.f;

    for (int kp = 0; kp < 128; kp += 64) {
        __syncthreads();
#pragma unroll
        for (int l = 0; l < 4; l++) {
            int lin = tid + l * 256;
            int row = lin >> 4;
            int kq  = lin & 15;
            float4 va = *(const float4*)(y   + (size_t)(m0 + row) * DD + kp + kq * 4);
            float4 vb = *(const float4*)(Wih + (size_t)(n0 + row) * DD + kp + kq * 4);
            As[kq * 4 + 0][row] = va.x; As[kq * 4 + 1][row] = va.y;
            As[kq * 4 + 2][row] = va.z; As[kq * 4 + 3][row] = va.w;
            Bs[kq * 4 + 0][row] = vb.x; Bs[kq * 4 + 1][row] = vb.y;
            Bs[kq * 4 + 2][row] = vb.z; Bs[kq * 4 + 3][row] = vb.w;
        }
        __syncthreads();
#pragma unroll
        for (int k = 0; k < 64; k++) {
            float4 av = *(const float4*)&As[k][ty * 4];
            float4 bv = *(const float4*)&Bs[k][tx * 4];
            float a[4] = {av.x, av.y, av.z, av.w};
            float b[4] = {bv.x, bv.y, bv.z, bv.w};
#pragma unroll
            for (int i = 0; i < 4; i++)
#pragma unroll
                for (int j = 0; j < 4; j++) acc[i][j] = fmaf(a[i], b[j], acc[i][j]);
        }
    }
#pragma unroll
    for (int j = 0; j < 4; j++) {
        float b = bih[n0 + tx * 4 + j];
#pragma unroll
        for (int i = 0; i < 4; i++) acc[i][j] += b;
    }
#pragma unroll
    for (int i = 0; i < 4; i++) {
        float* o = g_xproj + (size_t)(m0 + ty * 4 + i) * 768 + n0 + tx * 4;
        *(float4*)o = make_float4(acc[i][0], acc[i][1], acc[i][2], acc[i][3]);
    }
}

// ============================================================
// 2) GRU (R8 measured-good version): 32 clusters x 4 CTAs,
//    2 batches/cluster. j = tid&63, ks = tid>>6. Gates r,z weights
//    in regs; gate n in SMEM. smem reduce + 128-thread epilogue.
// ============================================================
__global__ void __cluster_dims__(4, 1, 1) __launch_bounds__(512, 1)
gru_kernel(const float* __restrict__ Whh, const float* __restrict__ bhh)
{
    extern __shared__ float dsm[];
    float* h_s = dsm + GRU_HS_OFF;     // [(ph*2 + b)*HH + idx]
    float* red = dsm + GRU_RED_OFF;    // [j*49 + slot]
    float* Wn  = dsm + GRU_WN_OFF;     // [j*GRU_WN_STR + k]

    const int tid  = threadIdx.x;
    const int j    = tid & 63;
    const int ks   = tid >> 6;                 // 0..7 (k-slice of 32)
    const int rank = blockIdx.x & 3;
    const int u0   = rank * 64;
    const int bg   = (blockIdx.x >> 2) * 2;    // global batch base

    // register-resident W for gates r,z: rows g*256+u0+j, cols ks*32..+32
    float W[2][32];
#pragma unroll
    for (int g = 0; g < 2; g++) {
        const float4* wp = (const float4*)(Whh + (size_t)(g * HH + u0 + j) * HH + ks * 32);
#pragma unroll
        for (int q = 0; q < 8; q++) {
            float4 v = wp[q];
            W[g][4 * q + 0] = v.x; W[g][4 * q + 1] = v.y;
            W[g][4 * q + 2] = v.z; W[g][4 * q + 3] = v.w;
        }
    }
    // SMEM-resident gate-n weights
    {
        const float4* wp = (const float4*)(Whh + (size_t)(2 * HH + u0 + j) * HH + ks * 32);
        float4* dp = (float4*)&Wn[j * GRU_WN_STR + ks * 32];
#pragma unroll
        for (int q = 0; q < 8; q++) dp[q] = wp[q];
    }
    float bh0 = 0.f, bh1 = 0.f, bh2 = 0.f;
    if (tid < 128) {
        int jr = tid & 63;
        bh0 = bhh[u0 + jr];
        bh1 = bhh[HH + u0 + jr];
        bh2 = bhh[2 * HH + u0 + jr];
    }
    for (int i = tid; i < 2 * 2 * HH; i += 512) h_s[i] = 0.f;

    uint32_t hbase;
    asm("{ .reg .u64 t; cvta.to.shared.u64 t, %1; cvt.u32.u64 %0, t; }"
        : "=r"(hbase) : "l"((void*)h_s));

    __syncthreads();
    asm volatile("barrier.cluster.arrive.aligned;" ::: "memory");
    asm volatile("barrier.cluster.wait.aligned;" ::: "memory");

    for (int t = 0; t < TT; t++) {
        const int ph = t & 1;
        float xr = 0.f, xz = 0.f, xn = 0.f;
        if (tid < 128) {
            const int b = tid >> 6, jr = tid & 63;
            const float* xp = g_xproj + ((size_t)(bg + b) * TT + t) * 768 + u0 + jr;
            xr = xp[0]; xz = xp[HH]; xn = xp[2 * HH];
        }
        // partial dots: 3 gates x 2 batches over this thread's 32 k's
        float a00 = 0.f, a01 = 0.f, a10 = 0.f, a11 = 0.f, a20 = 0.f, a21 = 0.f;
        const float4* h0v = (const float4*)&h_s[(ph * 2 + 0) * HH + ks * 32];
        const float4* h1v = (const float4*)&h_s[(ph * 2 + 1) * HH + ks * 32];
        const float4* wnv = (const float4*)&Wn[j * GRU_WN_STR + ks * 32];
#pragma unroll
        for (int q = 0; q < 8; q++) {
            float4 va = h0v[q];
            float4 vb = h1v[q];
            float4 wn = wnv[q];
            float ha[4] = {va.x, va.y, va.z, va.w};
            float hb[4] = {vb.x, vb.y, vb.z, vb.w};
            float wnn[4] = {wn.x, wn.y, wn.z, wn.w};
#pragma unroll
            for (int c = 0; c < 4; c++) {
                float w0 = W[0][4 * q + c], w1 = W[1][4 * q + c], w2 = wnn[c];
                a00 = fmaf(w0, ha[c], a00); a01 = fmaf(w0, hb[c], a01);
                a10 = fmaf(w1, ha[c], a10); a11 = fmaf(w1, hb[c], a11);
                a20 = fmaf(w2, ha[c], a20); a21 = fmaf(w2, hb[c], a21);
            }
        }
        float* rbase = red + j * 49;
        rbase[ks]      = a00; rbase[8 + ks]  = a01;
        rbase[16 + ks] = a10; rbase[24 + ks] = a11;
        rbase[32 + ks] = a20; rbase[40 + ks] = a21;
        __syncthreads();
        if (tid < 128) {
            const int b = tid >> 6, jr = tid & 63;
            const float* rp = red + jr * 49 + b * 8;
            float sr = bh0, sz = bh1, sn = bh2;
#pragma unroll
            for (int k = 0; k < 8; k++) {
                sr += rp[k]; sz += rp[16 + k]; sn += rp[32 + k];
            }
            float r = 1.f / (1.f + expf(-(xr + sr)));
            float z = 1.f / (1.f + expf(-(xz + sz)));
            float n = tanhf(xn + r * sn);
            float hold = h_s[(ph * 2 + b) * HH + u0 + jr];
            float hnew = fmaf(z, hold - n, n);   // (1-z)*n + z*h
            g_enc[((size_t)(bg + b) * TT + t) * HH + u0 + jr] = hnew;
            uint32_t laddr = hbase + (uint32_t)(((((ph ^ 1) * 2 + b) * HH) + u0 + jr) * 4);
#pragma unroll
            for (int p = 0; p < 4; p++) {
                uint32_t raddr;
                asm("mapa.shared::cluster.u32 %0, %1, %2;" : "=r"(raddr) : "r"(laddr), "r"(p));
                asm volatile("st.shared::cluster.f32 [%0], %1;" :: "r"(raddr), "f"(hnew));
            }
        }
        asm volatile("barrier.cluster.arrive.aligned;" ::: "memory");
        asm volatile("barrier.cluster.wait.aligned;" ::: "memory");
    }
}

// ============================================================
// 3) heads: enc[16384,256] x W_all^T[256,96] + transforms + scatter
//    r: [0,8)=mean_z [8,16)=mean_x [16,32)=bd_z [32,96)=cov_x
//    Anchor (mean_x[b,0,:2]) computed in a per-block pre-pass.
// ============================================================
__global__ void __launch_bounds__(384) heads_kernel(
    const float* __restrict__ Wmz, const float* __restrict__ bmz,
    const float* __restrict__ Wmx, const float* __restrict__ bmx,
    const float* __restrict__ Wpz, const float* __restrict__ bpz,
    const float* __restrict__ Wcx, const float* __restrict__ bcx,
    float* __restrict__ out)
{
    __shared__ float encsm[256];
    __shared__ float red[384];
    __shared__ float anchor_sm[2];

    const int tid = threadIdx.x;
    const int r  = tid % 96;
    const int kc = tid / 96;

    const float* wrow;
    float bias;
    if (r < 8)       { wrow = Wmz + (size_t)r * HH;        bias = bmz[r]; }
    else if (r < 16) { wrow = Wmx + (size_t)(r - 8) * HH;  bias = bmx[r - 8]; }
    else if (r < 32) { wrow = Wpz + (size_t)(r - 16) * HH; bias = bpz[r - 16]; }
    else             { wrow = Wcx + (size_t)(r - 32) * HH; bias = bcx[r - 32]; }

    float W[64];
    {
        const float4* wp = (const float4*)(wrow + kc * 64);
#pragma unroll
        for (int q = 0; q < 16; q++) {
            float4 v = wp[q];
            W[4 * q + 0] = v.x; W[4 * q + 1] = v.y;
            W[4 * q + 2] = v.z; W[4 * q + 3] = v.w;
        }
    }

    const int row0 = blockIdx.x * 128;
    const int bbase = (blockIdx.x >> 1) << 8;   // t=0 row of this block's batch

    // anchor pre-pass: mean_x[b, 0, 0:2] (incl. bias)
    {
        if (tid < 64)
            *(float4*)&encsm[tid * 4] = *(const float4*)(g_enc + (size_t)bbase * HH + tid * 4);
        __syncthreads();
        float s = 0.f;
        const float4* ev = (const float4*)&encsm[kc * 64];
#pragma unroll
        for (int q = 0; q < 16; q++) {
            float4 v = ev[q];
            s = fmaf(W[4 * q + 0], v.x, s);
            s = fmaf(W[4 * q + 1], v.y, s);
            s = fmaf(W[4 * q + 2], v.z, s);
            s = fmaf(W[4 * q + 3], v.w, s);
        }
        red[kc * 96 + r] = s;
        __syncthreads();
        if (tid == 8 || tid == 9) {
            anchor_sm[tid - 8] =
                red[tid] + red[96 + tid] + red[192 + tid] + red[288 + tid] + bias;
        }
    }

    for (int i = 0; i < 128; i++) {
        const int row = row0 + i;
        __syncthreads();
        if (tid < 64) {
            *(float4*)&encsm[tid * 4] = *(const float4*)(g_enc + (size_t)row * HH + tid * 4);
        }
        __syncthreads();
        float s = 0.f;
        const float4* ev = (const float4*)&encsm[kc * 64];
#pragma unroll
        for (int q = 0; q < 16; q++) {
            float4 v = ev[q];
            s = fmaf(W[4 * q + 0], v.x, s);
            s = fmaf(W[4 * q + 1], v.y, s);
            s = fmaf(W[4 * q + 2], v.z, s);
            s = fmaf(W[4 * q + 3], v.w, s);
        }
        red[kc * 96 + r] = s;
        __syncthreads();
        if (tid < 96) {
            float v = red[tid] + red[96 + tid] + red[192 + tid] + red[288 + tid] + bias;
            const int b = row >> 8, t = row & 255;
            if (tid < 8) {
                out[OFF_MZ + (size_t)row * 8 + tid] = v;
            } else if (tid < 16) {
                int d = tid - 8;
                float a = (d < 2) ? anchor_sm[d] : 0.f;
                out[OFF_MX + (size_t)row * 8 + d] = v - a;
            } else if (tid < 32) {
                int d = tid - 16;
                if (d < 8) {
                    float sp = (v > 20.f) ? v : log1pf(expf(v));
                    out[OFF_CHOL + (((size_t)d * BB + b) * TT + t) * TT + t] = sp;
                } else {
                    int dz = d - 8;
                    if (t < TT - 1)
                        out[OFF_CHOL + (((size_t)dz * BB + b) * TT + t) * TT + (t + 1)] = v;
                }
            } else {
                out[OFF_CX + (size_t)row * 64 + (tid - 32)] = v;
            }
        }
    }
}

extern "C" void kernel_launch(void* const* d_in, const int* in_sizes, int n_in,
                              void* d_out, int out_size)
{
    const float* y    = (const float*)d_in[0];
    const float* Wih  = (const float*)d_in[1];
    const float* Whh  = (const float*)d_in[2];
    const float* bih  = (const float*)d_in[3];
    const float* bhh  = (const float*)d_in[4];
    const float* Wmz  = (const float*)d_in[5];
    const float* bmz  = (const float*)d_in[6];
    const float* Wmx  = (const float*)d_in[7];
    const float* bmx  = (const float*)d_in[8];
    const float* Wpz  = (const float*)d_in[9];
    const float* bpz  = (const float*)d_in[10];
    const float* Wcx  = (const float*)d_in[11];
    const float* bcx  = (const float*)d_in[12];
    float* out = (float*)d_out;

    cudaFuncSetAttribute(gru_kernel, cudaFuncAttributeMaxDynamicSharedMemorySize,
                         GRU_SMEM_BYTES);

    dim3 gx(256, 12);
    xproj_kernel<<<gx, 256>>>(y, Wih, bih, (float4*)(out + OFF_CHOL));

    gru_kernel<<<128, 512, GRU_SMEM_BYTES>>>(Whh, bhh);

    heads_kernel<<<128, 384>>>(Wmz, bmz, Wmx, bmx, Wpz, bpz, Wcx, bcx, out);
}